// round 12
// baseline (speedup 1.0000x reference)
#include <cuda_runtime.h>
#include <cuda_bf16.h>
#include <math.h>
#include <stdint.h>
#include <mma.h>

using namespace nvcuda;

#define NN     50000
#define NN_PAD 50048          // 391 * 128, so every GEMM CTA stores unguarded
#define EE     600000
#define DD     128
#define CC     128
#define GG     64
#define NCLS   10
#define NCAT   512
#define SCAN_BLKS 196         // ceil(NN/256)

// ---------------- scratch (static device globals; no allocation) ----------------
__device__ __align__(16) float g_q[NN_PAD * CC];
__device__ __align__(16) __nv_bfloat16 g_kv[NN_PAD * 256]; // per node: 128 bf16 k | 128 bf16 v
__device__ __align__(16) float g_h0[NN_PAD * CC];   // layer-0 output (POST-relu)
__device__ __align__(16) float g_h1[NN_PAD * CC];   // layer-1 GEMM skip buffer
__device__ __align__(16) float g_wh[2 * DD * NCAT]; // tf32-rounded [Wq|Wk|Wv|Ws] per layer
__device__ __align__(16) float g_bcat[2 * NCAT];
// CSR (rebuilt every call)
__device__ int g_deg[SCAN_BLKS * 256];
__device__ int g_rowptr[NN + 1];
__device__ int g_wpos[NN];
__device__ int g_srcs[EE];
__device__ int g_bsum[SCAN_BLKS];
__device__ int g_boff[SCAN_BLKS];
// pooling
__device__ __align__(16) float g_sums[GG * CC];
__device__ float g_cnt[GG];

// ---------------- helpers ----------------
__device__ __forceinline__ void red_add_v4(float* addr, float a, float b, float c, float d) {
    asm volatile("red.global.add.v4.f32 [%0], {%1, %2, %3, %4};"
                 :: "l"(addr), "f"(a), "f"(b), "f"(c), "f"(d) : "memory");
}

__device__ __forceinline__ void cp_async16(void* smem_dst, const void* gsrc, bool pred) {
    uint32_t sa = (uint32_t)__cvta_generic_to_shared(smem_dst);
    int sz = pred ? 16 : 0;
    asm volatile("cp.async.cg.shared.global [%0], [%1], 16, %2;"
                 :: "r"(sa), "l"(gsrc), "r"(sz));
}
#define CP_COMMIT() asm volatile("cp.async.commit_group;")
#define CP_WAIT(N)  asm volatile("cp.async.wait_group %0;" :: "n"(N))

// ---------------- init kernels ----------------
__global__ void init_pool_kernel() {
    int i = blockIdx.x * blockDim.x + threadIdx.x;
    if (i < GG * CC) g_sums[i] = 0.0f;
    if (i < GG) g_cnt[i] = 0.0f;
    if (i < SCAN_BLKS * 256) g_deg[i] = 0;   // covers NN with padding zeros
}

// ---------------- CSR build ----------------
__global__ void csr_hist_kernel(const int* __restrict__ dst) {
    int e = blockIdx.x * blockDim.x + threadIdx.x;
    if (e < EE) atomicAdd(&g_deg[dst[e]], 1);
}

__global__ void scan_partial_kernel() {
    __shared__ int s[256];
    int i = blockIdx.x * 256 + threadIdx.x;
    int v = g_deg[i];
    s[threadIdx.x] = v;
    __syncthreads();
    #pragma unroll
    for (int off = 128; off > 0; off >>= 1) {
        if (threadIdx.x < off) s[threadIdx.x] += s[threadIdx.x + off];
        __syncthreads();
    }
    if (threadIdx.x == 0) g_bsum[blockIdx.x] = s[0];
}

__global__ void scan_top_kernel() {
    __shared__ int s[256];
    int t = threadIdx.x;
    int v = (t < SCAN_BLKS) ? g_bsum[t] : 0;
    s[t] = v;
    __syncthreads();
    #pragma unroll
    for (int off = 1; off < 256; off <<= 1) {
        int u = (t >= off) ? s[t - off] : 0;
        __syncthreads();
        s[t] += u;
        __syncthreads();
    }
    if (t < SCAN_BLKS) g_boff[t] = s[t] - v;   // exclusive
}

__global__ void scan_final_kernel() {
    __shared__ int s[256];
    int t = threadIdx.x;
    int i = blockIdx.x * 256 + t;
    int v = g_deg[i];
    s[t] = v;
    __syncthreads();
    #pragma unroll
    for (int off = 1; off < 256; off <<= 1) {
        int u = (t >= off) ? s[t - off] : 0;
        __syncthreads();
        s[t] += u;
        __syncthreads();
    }
    int excl = s[t] - v + g_boff[blockIdx.x];
    if (i < NN) {
        g_rowptr[i] = excl;
        g_wpos[i]   = excl;
    }
    if (blockIdx.x == SCAN_BLKS - 1 && t == 255)
        g_rowptr[NN] = EE;
}

__global__ void csr_scatter_kernel(const int* __restrict__ src, const int* __restrict__ dst) {
    int e = blockIdx.x * blockDim.x + threadIdx.x;
    if (e >= EE) return;
    int pos = atomicAdd(&g_wpos[dst[e]], 1);
    g_srcs[pos] = src[e];
}

// ---------------- weight prep: both layers, concat + tf32 round ----------------
__global__ void prep_w_kernel(const float* __restrict__ Wq, const float* __restrict__ Wk,
                              const float* __restrict__ Wv, const float* __restrict__ Ws,
                              const float* __restrict__ bq, const float* __restrict__ bk,
                              const float* __restrict__ bv, const float* __restrict__ bs)
{
    int l = blockIdx.y;
    int i = blockIdx.x * 256 + threadIdx.x;
    if (i < DD * NCAT) {
        int k = i >> 9, nc = i & (NCAT - 1);
        int o = nc >> 7, n = nc & 127;
        const float* W = (o == 0) ? Wq : (o == 1) ? Wk : (o == 2) ? Wv : Ws;
        g_wh[l * DD * NCAT + i] = wmma::__float_to_tf32(W[l * DD * CC + k * CC + n]);
    }
    if (i < NCAT) {
        int o = i >> 7, n = i & 127;
        const float* B = (o == 0) ? bq : (o == 1) ? bk : (o == 2) ? bv : bs;
        g_bcat[l * NCAT + i] = B[l * CC + n];
    }
}

// ---------------- wmma tf32 GEMM, cp.async double-buffered ----------------
// dynamic smem (floats): A buf0 @0 [128*36], A buf1 @4608, B buf0 @9216 [32*132],
// B buf1 @13440; total 17664 floats = 70656 B. Epilogue stage (128*132) reuses [0..16896).
#define SA0 0
#define SA1 4608
#define SB0 9216
#define SB1 13440
#define SM_FLOATS 17664
#define SM_BYTES  (SM_FLOATS * 4)

__device__ __forceinline__ void gemm_prefetch(
    float* smem, int sa, int sb, const float* __restrict__ Xp,
    const float* __restrict__ Wl, int row0, int k0, int o, bool guard, int tid)
{
    #pragma unroll
    for (int i = tid; i < 1024; i += 256) {       // A: 128 rows x 8 float4 (32 k)
        int r = i >> 3, c4 = i & 7;
        bool ok = !guard || (row0 + r < NN);
        cp_async16(&smem[sa + r * 36 + c4 * 4],
                   Xp + (size_t)(row0 + r) * DD + k0 + c4 * 4, ok);
    }
    #pragma unroll
    for (int i = tid; i < 1024; i += 256) {       // B: 32 rows x 32 float4 (128 n)
        int r = i >> 5, c4 = i & 31;
        cp_async16(&smem[sb + r * 132 + c4 * 4],
                   Wl + (size_t)(k0 + r) * NCAT + o * 128 + c4 * 4, true);
    }
}

__device__ __forceinline__ void gemm_chunk(
    const float* smem, int sa, int sb, int wr, int wc,
    wmma::fragment<wmma::accumulator, 16, 16, 8, float> (&acc)[2][4])
{
    #pragma unroll
    for (int kk = 0; kk < 32; kk += 8) {
        wmma::fragment<wmma::matrix_b, 16, 16, 8, wmma::precision::tf32, wmma::row_major> bf[4];
        #pragma unroll
        for (int j = 0; j < 4; j++)
            wmma::load_matrix_sync(bf[j], &smem[sb + kk * 132 + wc * 64 + j * 16], 132);
        #pragma unroll
        for (int i = 0; i < 2; i++) {
            wmma::fragment<wmma::matrix_a, 16, 16, 8, wmma::precision::tf32, wmma::row_major> af;
            wmma::load_matrix_sync(af, &smem[sa + (wr * 32 + i * 16) * 36 + kk], 36);
            #pragma unroll
            for (int j = 0; j < 4; j++)
                wmma::mma_sync(acc[i][j], af, bf[j], acc[i][j]);
        }
    }
}

__global__ __launch_bounds__(256, 2) void gemm_wmma_kernel(
    const float* __restrict__ X,   // null => g_h0 (post-relu, padded)
    int layer)
{
    extern __shared__ float smem[];
    const int tid = threadIdx.x;
    const int w   = tid >> 5;
    const int wr  = w >> 1;          // 0..3 : rows wr*32..+32
    const int wc  = w & 1;           // 0..1 : cols wc*64..+64
    const int o   = blockIdx.y;
    const int row0 = blockIdx.x * 128;
    const bool guard = (X != nullptr);   // layer-0 input x has exactly NN rows
    const float* Xp = guard ? X : g_h0;
    const float* Wl = g_wh + (size_t)layer * DD * NCAT;

    wmma::fragment<wmma::accumulator, 16, 16, 8, float> acc[2][4];
    #pragma unroll
    for (int i = 0; i < 2; i++)
        #pragma unroll
        for (int j = 0; j < 4; j++)
            wmma::fill_fragment(acc[i][j], 0.0f);

    gemm_prefetch(smem, SA0, SB0, Xp, Wl, row0, 0, o, guard, tid);
    CP_COMMIT();

    #pragma unroll
    for (int kc = 0; kc < 4; kc++) {
        const int sa = (kc & 1) ? SA1 : SA0;
        const int sb = (kc & 1) ? SB1 : SB0;
        if (kc < 3) {
            gemm_prefetch(smem, (kc & 1) ? SA0 : SA1, (kc & 1) ? SB0 : SB1,
                          Xp, Wl, row0, (kc + 1) * 32, o, guard, tid);
            CP_COMMIT();
            CP_WAIT(1);
        } else {
            CP_WAIT(0);
        }
        __syncthreads();
        gemm_chunk(smem, sa, sb, wr, wc, acc);
        __syncthreads();
    }

    // unified epilogue: stage full 128x128 tile in smem (ld 132), then copy out + bias
    #pragma unroll
    for (int i = 0; i < 2; i++)
        #pragma unroll
        for (int j = 0; j < 4; j++)
            wmma::store_matrix_sync(&smem[(wr * 32 + i * 16) * 132 + wc * 64 + j * 16],
                                    acc[i][j], 132, wmma::mem_row_major);
    __syncthreads();

    const float* Bv = g_bcat + layer * NCAT + o * 128;
    if (o == 0 || o == 3) {
        float* O = (o == 0) ? g_q : ((layer == 0) ? g_h0 : g_h1);
        const int c4 = tid & 31;                    // fixed column group per thread
        float4 b4 = *reinterpret_cast<const float4*>(&Bv[c4 * 4]);
        #pragma unroll
        for (int r = tid >> 5; r < 128; r += 8) {
            float4 v;
            v.x = smem[r * 132 + c4 * 4 + 0] + b4.x;
            v.y = smem[r * 132 + c4 * 4 + 1] + b4.y;
            v.z = smem[r * 132 + c4 * 4 + 2] + b4.z;
            v.w = smem[r * 132 + c4 * 4 + 3] + b4.w;
            *reinterpret_cast<float4*>(&O[(size_t)(row0 + r) * CC + c4 * 4]) = v;
        }
    } else {
        const int colbase2 = (o == 1) ? 0 : 64;     // bf16x2 units within 256-bf16 row
        const int c2 = tid & 63;                    // fixed bf16x2 column per thread
        float blo = Bv[c2 * 2], bhi = Bv[c2 * 2 + 1];
        #pragma unroll
        for (int r = tid >> 6; r < 128; r += 4) {
            float lo = smem[r * 132 + c2 * 2]     + blo;
            float hi = smem[r * 132 + c2 * 2 + 1] + bhi;
            reinterpret_cast<__nv_bfloat162*>(g_kv)[(size_t)(row0 + r) * 128 +
                                                    colbase2 + c2] = __floats2bfloat162_rn(lo, hi);
        }
    }
}

// ---------------- fused attention: warp per dst node, online softmax, unroll 4 ----
__device__ __forceinline__ void kv_unpack(uint2 u, float2& a, float2& b) {
    a = __bfloat1622float2(*reinterpret_cast<__nv_bfloat162*>(&u.x));
    b = __bfloat1622float2(*reinterpret_cast<__nv_bfloat162*>(&u.y));
}

__device__ __forceinline__ void online_update(
    float sc, float2 va, float2 vb, float& m, float& den, float4& acc)
{
    float mn = fmaxf(m, sc);
    float corr = __expf(m - mn);
    float wgt = __expf(sc - mn);
    den = den * corr + wgt;
    acc.x = acc.x * corr + wgt * va.x;
    acc.y = acc.y * corr + wgt * va.y;
    acc.z = acc.z * corr + wgt * vb.x;
    acc.w = acc.w * corr + wgt * vb.y;
    m = mn;
}

__global__ __launch_bounds__(256) void attn_kernel(int layer, const int* __restrict__ batch)
{
    int t = blockIdx.x * 256 + threadIdx.x;
    int d = t >> 5;
    int lane = t & 31;
    if (d >= NN) return;
    int beg = g_rowptr[d];
    int end = g_rowptr[d + 1];

    float4 qa = reinterpret_cast<const float4*>(g_q)[(size_t)d * 32 + lane];

    float m = -INFINITY;
    float den = 0.0f;
    float4 acc = make_float4(0.f, 0.f, 0.f, 0.f);

    const uint2* kvb = reinterpret_cast<const uint2*>(g_kv);  // node row = 64 uint2

    int e = beg;
    for (; e + 4 <= end; e += 4) {
        int s0 = g_srcs[e],     s1 = g_srcs[e + 1];
        int s2 = g_srcs[e + 2], s3 = g_srcs[e + 3];
        uint2 uk0 = kvb[(size_t)s0 * 64 + lane];
        uint2 uk1 = kvb[(size_t)s1 * 64 + lane];
        uint2 uk2 = kvb[(size_t)s2 * 64 + lane];
        uint2 uk3 = kvb[(size_t)s3 * 64 + lane];
        uint2 uv0 = kvb[(size_t)s0 * 64 + 32 + lane];
        uint2 uv1 = kvb[(size_t)s1 * 64 + 32 + lane];
        uint2 uv2 = kvb[(size_t)s2 * 64 + 32 + lane];
        uint2 uv3 = kvb[(size_t)s3 * 64 + 32 + lane];
        float2 ka0, kb0, ka1, kb1, ka2, kb2, ka3, kb3;
        kv_unpack(uk0, ka0, kb0); kv_unpack(uk1, ka1, kb1);
        kv_unpack(uk2, ka2, kb2); kv_unpack(uk3, ka3, kb3);
        float d0 = qa.x * ka0.x + qa.y * ka0.y + qa.z * kb0.x + qa.w * kb0.y;
        float d1 = qa.x * ka1.x + qa.y * ka1.y + qa.z * kb1.x + qa.w * kb1.y;
        float d2 = qa.x * ka2.x + qa.y * ka2.y + qa.z * kb2.x + qa.w * kb2.y;
        float d3 = qa.x * ka3.x + qa.y * ka3.y + qa.z * kb3.x + qa.w * kb3.y;
        #pragma unroll
        for (int o = 16; o > 0; o >>= 1) {
            d0 += __shfl_xor_sync(0xffffffffu, d0, o);
            d1 += __shfl_xor_sync(0xffffffffu, d1, o);
            d2 += __shfl_xor_sync(0xffffffffu, d2, o);
            d3 += __shfl_xor_sync(0xffffffffu, d3, o);
        }
        float2 va, vb;
        kv_unpack(uv0, va, vb);
        online_update(d0 * 0.08838834764831843f, va, vb, m, den, acc);
        kv_unpack(uv1, va, vb);
        online_update(d1 * 0.08838834764831843f, va, vb, m, den, acc);
        kv_unpack(uv2, va, vb);
        online_update(d2 * 0.08838834764831843f, va, vb, m, den, acc);
        kv_unpack(uv3, va, vb);
        online_update(d3 * 0.08838834764831843f, va, vb, m, den, acc);
    }
    for (; e < end; e++) {
        int s = g_srcs[e];
        uint2 uk = kvb[(size_t)s * 64 + lane];
        uint2 uv = kvb[(size_t)s * 64 + 32 + lane];
        float2 ka, kb;
        kv_unpack(uk, ka, kb);
        float dot = qa.x * ka.x + qa.y * ka.y + qa.z * kb.x + qa.w * kb.y;
        #pragma unroll
        for (int o = 16; o > 0; o >>= 1) dot += __shfl_xor_sync(0xffffffffu, dot, o);
        float2 va, vb;
        kv_unpack(uv, va, vb);
        online_update(dot * 0.08838834764831843f, va, vb, m, den, acc);
    }

    float* O = (layer == 0) ? g_h0 : g_h1;
    float4 o = reinterpret_cast<const float4*>(O)[(size_t)d * 32 + lane];
    if (beg < end) {
        float inv = 1.0f / den;
        o.x += acc.x * inv;
        o.y += acc.y * inv;
        o.z += acc.z * inv;
        o.w += acc.w * inv;
    }
    o.x = fmaxf(o.x, 0.f); o.y = fmaxf(o.y, 0.f);
    o.z = fmaxf(o.z, 0.f); o.w = fmaxf(o.w, 0.f);

    if (batch == nullptr) {
        reinterpret_cast<float4*>(O)[(size_t)d * 32 + lane] = o;
    } else {
        int g = batch[d];
        red_add_v4(&g_sums[g * CC + lane * 4], o.x, o.y, o.z, o.w);
        if (lane == 0) atomicAdd(&g_cnt[g], 1.0f);
    }
}

// ---------------- classifier + log_softmax ----------------
__global__ void final_kernel(const float* __restrict__ W_fc,
                             const float* __restrict__ b_fc,
                             float* __restrict__ out)
{
    int g = blockIdx.x;
    int j = threadIdx.x;
    __shared__ float sl[12];
    float inv = 1.0f / fmaxf(g_cnt[g], 1.0f);
    if (j < NCLS) {
        float acc = b_fc[j];
        for (int c = 0; c < CC; c++)
            acc += g_sums[g * CC + c] * inv * W_fc[c * NCLS + j];
        sl[j] = acc;
    }
    __syncwarp();
    if (j == 0) {
        float mx = sl[0];
        for (int i = 1; i < NCLS; i++) mx = fmaxf(mx, sl[i]);
        float ssum = 0.f;
        for (int i = 0; i < NCLS; i++) ssum += expf(sl[i] - mx);
        sl[10] = mx + logf(ssum);
    }
    __syncwarp();
    if (j < NCLS) out[g * NCLS + j] = sl[j] - sl[10];
}

// ---------------- launch ----------------
extern "C" void kernel_launch(void* const* d_in, const int* in_sizes, int n_in,
                              void* d_out, int out_size)
{
    const float* x    = (const float*)d_in[0];
    const int*   ei   = (const int*)d_in[1];
    const int*   batch= (const int*)d_in[2];
    const float* Wq   = (const float*)d_in[3];
    const float* bq   = (const float*)d_in[4];
    const float* Wk   = (const float*)d_in[5];
    const float* bk   = (const float*)d_in[6];
    const float* Wv   = (const float*)d_in[7];
    const float* bv   = (const float*)d_in[8];
    const float* Ws   = (const float*)d_in[9];
    const float* bs   = (const float*)d_in[10];
    const float* W_fc = (const float*)d_in[11];
    const float* b_fc = (const float*)d_in[12];
    float* out = (float*)d_out;

    const int* src = ei;
    const int* dst = ei + EE;

    // side stream + events for the CSR-build fork (created once; no device memory)
    static cudaStream_t s2 = nullptr;
    static cudaEvent_t evFork = nullptr, evJoin = nullptr;
    if (s2 == nullptr) {
        cudaStreamCreateWithFlags(&s2, cudaStreamNonBlocking);
        cudaEventCreateWithFlags(&evFork, cudaEventDisableTiming);
        cudaEventCreateWithFlags(&evJoin, cudaEventDisableTiming);
        cudaFuncSetAttribute(gemm_wmma_kernel,
                             cudaFuncAttributeMaxDynamicSharedMemorySize, SM_BYTES);
    }

    const int gemm_gx  = (NN + 127) / 128;          // 391
    const int edge_gx  = (EE + 255) / 256;          // 2344
    const int warp_gx  = (NN * 32 + 255) / 256;     // 6250
    const int prep_gx  = (DD * NCAT + 255) / 256;   // 256

    // fork: CSR build (+ pool init) runs concurrently with prep_w + gemm0
    cudaEventRecord(evFork, 0);
    cudaStreamWaitEvent(s2, evFork, 0);
    init_pool_kernel<<<SCAN_BLKS, 256, 0, s2>>>();
    csr_hist_kernel<<<edge_gx, 256, 0, s2>>>(dst);
    scan_partial_kernel<<<SCAN_BLKS, 256, 0, s2>>>();
    scan_top_kernel<<<1, 256, 0, s2>>>();
    scan_final_kernel<<<SCAN_BLKS, 256, 0, s2>>>();
    csr_scatter_kernel<<<edge_gx, 256, 0, s2>>>(src, dst);
    cudaEventRecord(evJoin, s2);

    // main stream: weight prep + layer-0 GEMM overlap the CSR build
    prep_w_kernel<<<dim3(prep_gx, 2), 256>>>(Wq, Wk, Wv, Ws, bq, bk, bv, bs);
    gemm_wmma_kernel<<<dim3(gemm_gx, 4), 256, SM_BYTES>>>(x, 0);

    // join before attention consumes rowptr/srcs
    cudaStreamWaitEvent(0, evJoin, 0);
    attn_kernel<<<warp_gx, 256>>>(0, nullptr);
    gemm_wmma_kernel<<<dim3(gemm_gx, 4), 256, SM_BYTES>>>(nullptr, 1);
    attn_kernel<<<warp_gx, 256>>>(1, batch);     // fused mean-pool

    final_kernel<<<GG, 32>>>(W_fc, b_fc, out);
}

// round 13
// speedup vs baseline: 2.2084x; 2.2084x over previous
#include <cuda_runtime.h>
#include <cuda_bf16.h>
#include <math.h>
#include <stdint.h>
#include <mma.h>

using namespace nvcuda;

#define NN     50000
#define NN_PAD 50048          // 391 * 128, so every GEMM CTA stores unguarded
#define EE     600000
#define DD     128
#define CC     128
#define GG     64
#define NCLS   10
#define NCAT   512
#define SCAN_BLKS 196         // ceil(NN/256)

// ---------------- scratch (static device globals; no allocation) ----------------
__device__ __align__(16) __nv_bfloat16 g_qb[NN_PAD * 128]; // per node: 128 bf16 q
__device__ __align__(16) __nv_bfloat16 g_kv[NN_PAD * 256]; // per node: 128 bf16 k | 128 bf16 v
__device__ __align__(16) float g_h0[NN_PAD * CC];   // layer-0 output (POST-relu)
__device__ __align__(16) float g_h1[NN_PAD * CC];   // layer-1 GEMM skip buffer
__device__ __align__(16) float g_wh[2 * DD * NCAT]; // tf32-rounded [Wq|Wk|Wv|Ws] per layer
__device__ __align__(16) float g_bcat[2 * NCAT];
// CSR (rebuilt every call)
__device__ int g_deg[SCAN_BLKS * 256];
__device__ int g_rowptr[NN + 1];
__device__ int g_wpos[NN];
__device__ int g_srcs[EE];
__device__ int g_bsum[SCAN_BLKS];
__device__ int g_boff[SCAN_BLKS];
// pooling
__device__ __align__(16) float g_sums[GG * CC];
__device__ float g_cnt[GG];

// ---------------- helpers ----------------
__device__ __forceinline__ void red_add_v4(float* addr, float a, float b, float c, float d) {
    asm volatile("red.global.add.v4.f32 [%0], {%1, %2, %3, %4};"
                 :: "l"(addr), "f"(a), "f"(b), "f"(c), "f"(d) : "memory");
}

// ---------------- init kernels ----------------
__global__ void init_pool_kernel() {
    int i = blockIdx.x * blockDim.x + threadIdx.x;
    if (i < GG * CC) g_sums[i] = 0.0f;
    if (i < GG) g_cnt[i] = 0.0f;
    if (i < SCAN_BLKS * 256) g_deg[i] = 0;   // covers NN with padding zeros
}

// ---------------- CSR build ----------------
__global__ void csr_hist_kernel(const int* __restrict__ dst) {
    int e = blockIdx.x * blockDim.x + threadIdx.x;
    if (e < EE) atomicAdd(&g_deg[dst[e]], 1);
}

__global__ void scan_partial_kernel() {
    __shared__ int s[256];
    int i = blockIdx.x * 256 + threadIdx.x;
    int v = g_deg[i];
    s[threadIdx.x] = v;
    __syncthreads();
    #pragma unroll
    for (int off = 128; off > 0; off >>= 1) {
        if (threadIdx.x < off) s[threadIdx.x] += s[threadIdx.x + off];
        __syncthreads();
    }
    if (threadIdx.x == 0) g_bsum[blockIdx.x] = s[0];
}

__global__ void scan_top_kernel() {
    __shared__ int s[256];
    int t = threadIdx.x;
    int v = (t < SCAN_BLKS) ? g_bsum[t] : 0;
    s[t] = v;
    __syncthreads();
    #pragma unroll
    for (int off = 1; off < 256; off <<= 1) {
        int u = (t >= off) ? s[t - off] : 0;
        __syncthreads();
        s[t] += u;
        __syncthreads();
    }
    if (t < SCAN_BLKS) g_boff[t] = s[t] - v;   // exclusive
}

__global__ void scan_final_kernel() {
    __shared__ int s[256];
    int t = threadIdx.x;
    int i = blockIdx.x * 256 + t;
    int v = g_deg[i];
    s[t] = v;
    __syncthreads();
    #pragma unroll
    for (int off = 1; off < 256; off <<= 1) {
        int u = (t >= off) ? s[t - off] : 0;
        __syncthreads();
        s[t] += u;
        __syncthreads();
    }
    int excl = s[t] - v + g_boff[blockIdx.x];
    if (i < NN) {
        g_rowptr[i] = excl;
        g_wpos[i]   = excl;
    }
    if (blockIdx.x == SCAN_BLKS - 1 && t == 255)
        g_rowptr[NN] = EE;
}

__global__ void csr_scatter_kernel(const int* __restrict__ src, const int* __restrict__ dst) {
    int e = blockIdx.x * blockDim.x + threadIdx.x;
    if (e >= EE) return;
    int pos = atomicAdd(&g_wpos[dst[e]], 1);
    g_srcs[pos] = src[e];
}

// ---------------- weight prep: both layers, concat + tf32 round ----------------
__global__ void prep_w_kernel(const float* __restrict__ Wq, const float* __restrict__ Wk,
                              const float* __restrict__ Wv, const float* __restrict__ Ws,
                              const float* __restrict__ bq, const float* __restrict__ bk,
                              const float* __restrict__ bv, const float* __restrict__ bs)
{
    int l = blockIdx.y;
    int i = blockIdx.x * 256 + threadIdx.x;
    if (i < DD * NCAT) {
        int k = i >> 9, nc = i & (NCAT - 1);
        int o = nc >> 7, n = nc & 127;
        const float* W = (o == 0) ? Wq : (o == 1) ? Wk : (o == 2) ? Wv : Ws;
        g_wh[l * DD * NCAT + i] = wmma::__float_to_tf32(W[l * DD * CC + k * CC + n]);
    }
    if (i < NCAT) {
        int o = i >> 7, n = i & 127;
        const float* B = (o == 0) ? bq : (o == 1) ? bk : (o == 2) ? bv : bs;
        g_bcat[l * NCAT + i] = B[l * CC + n];
    }
}

// ---------------- wmma tf32 GEMM: Y[:, o*128:+128] = X @ W + b (R6/R11 tiling) ----
// slab 3 (skip) stores fp32; slabs 0 (q), 1 (k), 2 (v) convert to packed bf16
// via smem staging (two half-tile passes reusing the tile smem).
__global__ __launch_bounds__(256, 2) void gemm_wmma_kernel(
    const float* __restrict__ X,   // null => g_h0 (post-relu, padded)
    int layer)
{
    __shared__ float sbuf[128 * 36 + 32 * 132 + 16 * 132];   // sA | sB | sBias (43.8 KB)
    float* sA    = sbuf;
    float* sB    = sbuf + 128 * 36;
    float* sBias = sbuf + 128 * 36 + 32 * 132;

    const int tid = threadIdx.x;
    const int w   = tid >> 5;
    const int wr  = w >> 1;          // 0..3 : rows wr*32..+32
    const int wc  = w & 1;           // 0..1 : cols wc*64..+64
    const int o   = blockIdx.y;
    const int row0 = blockIdx.x * 128;
    const bool guard = (X != nullptr);   // layer-0 input x has exactly NN rows
    const float* Xp = guard ? X : g_h0;
    const float* Wl = g_wh + (size_t)layer * DD * NCAT;

    for (int i = tid; i < 16 * 128; i += 256) {
        int r = i >> 7, c = i & 127;
        sBias[r * 132 + c] = g_bcat[layer * NCAT + o * 128 + c];
    }
    __syncthreads();

    wmma::fragment<wmma::accumulator, 16, 16, 8, float> acc[2][4];
    #pragma unroll
    for (int i = 0; i < 2; i++)
        #pragma unroll
        for (int j = 0; j < 4; j++)
            wmma::load_matrix_sync(acc[i][j], &sBias[wc * 64 + j * 16], 132, wmma::mem_row_major);

    for (int k0 = 0; k0 < DD; k0 += 32) {
        __syncthreads();
        #pragma unroll
        for (int i = tid; i < 1024; i += 256) {
            int r = i >> 3, c4 = i & 7;
            float4 v = make_float4(0.f, 0.f, 0.f, 0.f);
            if (!guard || row0 + r < NN)
                v = reinterpret_cast<const float4*>(Xp)[(size_t)(row0 + r) * 32 + (k0 >> 2) + c4];
            *reinterpret_cast<float4*>(&sA[r * 36 + c4 * 4]) = v;
        }
        #pragma unroll
        for (int i = tid; i < 1024; i += 256) {
            int r = i >> 5, c4 = i & 31;
            *reinterpret_cast<float4*>(&sB[r * 132 + c4 * 4]) =
                *reinterpret_cast<const float4*>(&Wl[(size_t)(k0 + r) * NCAT + o * 128 + c4 * 4]);
        }
        __syncthreads();

        #pragma unroll
        for (int kk = 0; kk < 32; kk += 8) {
            wmma::fragment<wmma::matrix_b, 16, 16, 8, wmma::precision::tf32, wmma::row_major> bf[4];
            #pragma unroll
            for (int j = 0; j < 4; j++)
                wmma::load_matrix_sync(bf[j], &sB[kk * 132 + wc * 64 + j * 16], 132);
            #pragma unroll
            for (int i = 0; i < 2; i++) {
                wmma::fragment<wmma::matrix_a, 16, 16, 8, wmma::precision::tf32, wmma::row_major> af;
                wmma::load_matrix_sync(af, &sA[(wr * 32 + i * 16) * 36 + kk], 36);
                #pragma unroll
                for (int j = 0; j < 4; j++)
                    wmma::mma_sync(acc[i][j], af, bf[j], acc[i][j]);
            }
        }
    }

    if (o == 3) {
        float* O = (layer == 0) ? g_h0 : g_h1;
        #pragma unroll
        for (int i = 0; i < 2; i++)
            #pragma unroll
            for (int j = 0; j < 4; j++)
                wmma::store_matrix_sync(
                    O + (size_t)(row0 + wr * 32 + i * 16) * CC + wc * 64 + j * 16,
                    acc[i][j], CC, wmma::mem_row_major);
    } else {
        // q (o==0) / k (o==1) / v (o==2): stage half-tile in smem, convert to bf16
        // q rows are 64 bf16x2 wide; kv rows are 128 bf16x2 (k at 0, v at 64)
        __nv_bfloat162* dstb = (o == 0)
            ? reinterpret_cast<__nv_bfloat162*>(g_qb)
            : reinterpret_cast<__nv_bfloat162*>(g_kv);
        const int rstride2  = (o == 0) ? 64 : 128;
        const int colbase2  = (o == 2) ? 64 : 0;
        float* stage = sbuf;                      // 128 x 68 floats = 8704 <= 10944
        #pragma unroll
        for (int p = 0; p < 2; p++) {
            __syncthreads();
            if (wc == p) {
                #pragma unroll
                for (int i = 0; i < 2; i++)
                    #pragma unroll
                    for (int j = 0; j < 4; j++)
                        wmma::store_matrix_sync(
                            &stage[(size_t)(wr * 32 + i * 16) * 68 + j * 16],
                            acc[i][j], 68, wmma::mem_row_major);
            }
            __syncthreads();
            #pragma unroll
            for (int i = tid; i < 4096; i += 256) {
                int r = i >> 5, c2 = i & 31;      // 32 bf16x2 per 64-col half
                float lo = stage[r * 68 + c2 * 2];
                float hi = stage[r * 68 + c2 * 2 + 1];
                __nv_bfloat162 h2 = __floats2bfloat162_rn(lo, hi);
                dstb[(size_t)(row0 + r) * rstride2 + colbase2 + p * 32 + c2] = h2;
            }
        }
    }
}

// ---------------- fused attention: warp per dst node, online softmax, unroll 4 ----
// q/k/v all packed bf16. layer 0 writes post-relu h0; layer 1 (batch != null)
// fuses mean-pool reduce and skips the h1 store.
__device__ __forceinline__ void kv_unpack(uint2 u, float2& a, float2& b) {
    a = __bfloat1622float2(*reinterpret_cast<__nv_bfloat162*>(&u.x));
    b = __bfloat1622float2(*reinterpret_cast<__nv_bfloat162*>(&u.y));
}

__device__ __forceinline__ void online_update(
    float sc, float2 va, float2 vb, float& m, float& den, float4& acc)
{
    float mn = fmaxf(m, sc);
    float corr = __expf(m - mn);
    float wgt = __expf(sc - mn);
    den = den * corr + wgt;
    acc.x = acc.x * corr + wgt * va.x;
    acc.y = acc.y * corr + wgt * va.y;
    acc.z = acc.z * corr + wgt * vb.x;
    acc.w = acc.w * corr + wgt * vb.y;
    m = mn;
}

__global__ __launch_bounds__(256) void attn_kernel(int layer, const int* __restrict__ batch)
{
    int t = blockIdx.x * 256 + threadIdx.x;
    int d = t >> 5;
    int lane = t & 31;
    if (d >= NN) return;
    int beg = g_rowptr[d];
    int end = g_rowptr[d + 1];

    uint2 uq = reinterpret_cast<const uint2*>(g_qb)[(size_t)d * 32 + lane];
    float2 qa_, qb_;
    kv_unpack(uq, qa_, qb_);
    float4 qa = make_float4(qa_.x, qa_.y, qb_.x, qb_.y);

    float m = -INFINITY;
    float den = 0.0f;
    float4 acc = make_float4(0.f, 0.f, 0.f, 0.f);

    const uint2* kvb = reinterpret_cast<const uint2*>(g_kv);  // node row = 64 uint2

    int e = beg;
    for (; e + 4 <= end; e += 4) {
        int s0 = g_srcs[e],     s1 = g_srcs[e + 1];
        int s2 = g_srcs[e + 2], s3 = g_srcs[e + 3];
        uint2 uk0 = kvb[(size_t)s0 * 64 + lane];
        uint2 uk1 = kvb[(size_t)s1 * 64 + lane];
        uint2 uk2 = kvb[(size_t)s2 * 64 + lane];
        uint2 uk3 = kvb[(size_t)s3 * 64 + lane];
        uint2 uv0 = kvb[(size_t)s0 * 64 + 32 + lane];
        uint2 uv1 = kvb[(size_t)s1 * 64 + 32 + lane];
        uint2 uv2 = kvb[(size_t)s2 * 64 + 32 + lane];
        uint2 uv3 = kvb[(size_t)s3 * 64 + 32 + lane];
        float2 ka0, kb0, ka1, kb1, ka2, kb2, ka3, kb3;
        kv_unpack(uk0, ka0, kb0); kv_unpack(uk1, ka1, kb1);
        kv_unpack(uk2, ka2, kb2); kv_unpack(uk3, ka3, kb3);
        float d0 = qa.x * ka0.x + qa.y * ka0.y + qa.z * kb0.x + qa.w * kb0.y;
        float d1 = qa.x * ka1.x + qa.y * ka1.y + qa.z * kb1.x + qa.w * kb1.y;
        float d2 = qa.x * ka2.x + qa.y * ka2.y + qa.z * kb2.x + qa.w * kb2.y;
        float d3 = qa.x * ka3.x + qa.y * ka3.y + qa.z * kb3.x + qa.w * kb3.y;
        #pragma unroll
        for (int o = 16; o > 0; o >>= 1) {
            d0 += __shfl_xor_sync(0xffffffffu, d0, o);
            d1 += __shfl_xor_sync(0xffffffffu, d1, o);
            d2 += __shfl_xor_sync(0xffffffffu, d2, o);
            d3 += __shfl_xor_sync(0xffffffffu, d3, o);
        }
        float2 va, vb;
        kv_unpack(uv0, va, vb);
        online_update(d0 * 0.08838834764831843f, va, vb, m, den, acc);
        kv_unpack(uv1, va, vb);
        online_update(d1 * 0.08838834764831843f, va, vb, m, den, acc);
        kv_unpack(uv2, va, vb);
        online_update(d2 * 0.08838834764831843f, va, vb, m, den, acc);
        kv_unpack(uv3, va, vb);
        online_update(d3 * 0.08838834764831843f, va, vb, m, den, acc);
    }
    for (; e < end; e++) {
        int s = g_srcs[e];
        uint2 uk = kvb[(size_t)s * 64 + lane];
        uint2 uv = kvb[(size_t)s * 64 + 32 + lane];
        float2 ka, kb;
        kv_unpack(uk, ka, kb);
        float dot = qa.x * ka.x + qa.y * ka.y + qa.z * kb.x + qa.w * kb.y;
        #pragma unroll
        for (int o = 16; o > 0; o >>= 1) dot += __shfl_xor_sync(0xffffffffu, dot, o);
        float2 va, vb;
        kv_unpack(uv, va, vb);
        online_update(dot * 0.08838834764831843f, va, vb, m, den, acc);
    }

    float* O = (layer == 0) ? g_h0 : g_h1;
    float4 o = reinterpret_cast<const float4*>(O)[(size_t)d * 32 + lane];
    if (beg < end) {
        float inv = 1.0f / den;
        o.x += acc.x * inv;
        o.y += acc.y * inv;
        o.z += acc.z * inv;
        o.w += acc.w * inv;
    }
    o.x = fmaxf(o.x, 0.f); o.y = fmaxf(o.y, 0.f);
    o.z = fmaxf(o.z, 0.f); o.w = fmaxf(o.w, 0.f);

    if (batch == nullptr) {
        reinterpret_cast<float4*>(O)[(size_t)d * 32 + lane] = o;
    } else {
        int g = batch[d];
        red_add_v4(&g_sums[g * CC + lane * 4], o.x, o.y, o.z, o.w);
        if (lane == 0) atomicAdd(&g_cnt[g], 1.0f);
    }
}

// ---------------- classifier + log_softmax ----------------
__global__ void final_kernel(const float* __restrict__ W_fc,
                             const float* __restrict__ b_fc,
                             float* __restrict__ out)
{
    int g = blockIdx.x;
    int j = threadIdx.x;
    __shared__ float sl[12];
    float inv = 1.0f / fmaxf(g_cnt[g], 1.0f);
    if (j < NCLS) {
        float acc = b_fc[j];
        for (int c = 0; c < CC; c++)
            acc += g_sums[g * CC + c] * inv * W_fc[c * NCLS + j];
        sl[j] = acc;
    }
    __syncwarp();
    if (j == 0) {
        float mx = sl[0];
        for (int i = 1; i < NCLS; i++) mx = fmaxf(mx, sl[i]);
        float ssum = 0.f;
        for (int i = 0; i < NCLS; i++) ssum += expf(sl[i] - mx);
        sl[10] = mx + logf(ssum);
    }
    __syncwarp();
    if (j < NCLS) out[g * NCLS + j] = sl[j] - sl[10];
}

// ---------------- launch ----------------
extern "C" void kernel_launch(void* const* d_in, const int* in_sizes, int n_in,
                              void* d_out, int out_size)
{
    const float* x    = (const float*)d_in[0];
    const int*   ei   = (const int*)d_in[1];
    const int*   batch= (const int*)d_in[2];
    const float* Wq   = (const float*)d_in[3];
    const float* bq   = (const float*)d_in[4];
    const float* Wk   = (const float*)d_in[5];
    const float* bk   = (const float*)d_in[6];
    const float* Wv   = (const float*)d_in[7];
    const float* bv   = (const float*)d_in[8];
    const float* Ws   = (const float*)d_in[9];
    const float* bs   = (const float*)d_in[10];
    const float* W_fc = (const float*)d_in[11];
    const float* b_fc = (const float*)d_in[12];
    float* out = (float*)d_out;

    const int* src = ei;
    const int* dst = ei + EE;

    // side stream + events for the CSR-build fork (created once; no device memory)
    static cudaStream_t s2 = nullptr;
    static cudaEvent_t evFork = nullptr, evJoin = nullptr;
    if (s2 == nullptr) {
        cudaStreamCreateWithFlags(&s2, cudaStreamNonBlocking);
        cudaEventCreateWithFlags(&evFork, cudaEventDisableTiming);
        cudaEventCreateWithFlags(&evJoin, cudaEventDisableTiming);
    }

    const int gemm_gx  = (NN + 127) / 128;          // 391
    const int edge_gx  = (EE + 255) / 256;          // 2344
    const int warp_gx  = (NN * 32 + 255) / 256;     // 6250
    const int prep_gx  = (DD * NCAT + 255) / 256;   // 256

    // fork for the CSR build; submission order places gemm0 at launch #4 so the
    // profiler (-s skip) finally captures the GEMM instead of a scan kernel.
    cudaEventRecord(evFork, 0);
    cudaStreamWaitEvent(s2, evFork, 0);

    prep_w_kernel<<<dim3(prep_gx, 2), 256>>>(Wq, Wk, Wv, Ws, bq, bk, bv, bs);   // #1
    init_pool_kernel<<<SCAN_BLKS, 256, 0, s2>>>();                              // #2
    csr_hist_kernel<<<edge_gx, 256, 0, s2>>>(dst);                              // #3
    gemm_wmma_kernel<<<dim3(gemm_gx, 4), 256>>>(x, 0);                          // #4 (profiled)
    scan_partial_kernel<<<SCAN_BLKS, 256, 0, s2>>>();                           // #5
    scan_top_kernel<<<1, 256, 0, s2>>>();
    scan_final_kernel<<<SCAN_BLKS, 256, 0, s2>>>();
    csr_scatter_kernel<<<edge_gx, 256, 0, s2>>>(src, dst);
    cudaEventRecord(evJoin, s2);

    // join before attention consumes rowptr/srcs
    cudaStreamWaitEvent(0, evJoin, 0);
    attn_kernel<<<warp_gx, 256>>>(0, nullptr);
    gemm_wmma_kernel<<<dim3(gemm_gx, 4), 256>>>(nullptr, 1);
    attn_kernel<<<warp_gx, 256>>>(1, batch);     // fused mean-pool

    final_kernel<<<GG, 32>>>(W_fc, b_fc, out);
}

// round 14
// speedup vs baseline: 2.9891x; 1.3535x over previous
#include <cuda_runtime.h>
#include <cuda_bf16.h>
#include <math.h>
#include <stdint.h>
#include <mma.h>

using namespace nvcuda;

#define NN     50000
#define NN_PAD 50048          // 391 * 128, so every GEMM CTA stores unguarded
#define EE     600000
#define DD     128
#define CC     128
#define GG     64
#define NCLS   10
#define NCAT   512
#define SCAN_BLKS 196         // ceil(NN/256)

// ---------------- scratch (static device globals; no allocation) ----------------
__device__ __align__(16) __nv_bfloat16 g_qb[NN_PAD * 128]; // per node: 128 bf16 q
__device__ __align__(16) __nv_bfloat16 g_kv[NN_PAD * 256]; // per node: 128 bf16 k | 128 bf16 v
__device__ __align__(16) float g_h0[NN_PAD * CC];   // layer-0 output (POST-relu)
__device__ __align__(16) float g_h1[NN_PAD * CC];   // layer-1 GEMM skip buffer
__device__ __align__(16) __nv_bfloat16 g_whb[2 * DD * NCAT]; // bf16 [Wq|Wk|Wv|Ws] per layer
__device__ __align__(16) float g_bcat[2 * NCAT];
// CSR (rebuilt every call)
__device__ int g_deg[SCAN_BLKS * 256];
__device__ int g_rowptr[NN + 1];
__device__ int g_wpos[NN];
__device__ int g_srcs[EE];
__device__ int g_bsum[SCAN_BLKS];
__device__ int g_boff[SCAN_BLKS];
// pooling
__device__ __align__(16) float g_sums[GG * CC];
__device__ float g_cnt[GG];

// ---------------- helpers ----------------
__device__ __forceinline__ void red_add_v4(float* addr, float a, float b, float c, float d) {
    asm volatile("red.global.add.v4.f32 [%0], {%1, %2, %3, %4};"
                 :: "l"(addr), "f"(a), "f"(b), "f"(c), "f"(d) : "memory");
}

// ---------------- init kernels ----------------
__global__ void init_pool_kernel() {
    int i = blockIdx.x * blockDim.x + threadIdx.x;
    if (i < GG * CC) g_sums[i] = 0.0f;
    if (i < GG) g_cnt[i] = 0.0f;
    if (i < SCAN_BLKS * 256) g_deg[i] = 0;   // covers NN with padding zeros
}

// ---------------- CSR build ----------------
__global__ void csr_hist_kernel(const int* __restrict__ dst) {
    int e = blockIdx.x * blockDim.x + threadIdx.x;
    if (e < EE) atomicAdd(&g_deg[dst[e]], 1);
}

__global__ void scan_partial_kernel() {
    __shared__ int s[256];
    int i = blockIdx.x * 256 + threadIdx.x;
    int v = g_deg[i];
    s[threadIdx.x] = v;
    __syncthreads();
    #pragma unroll
    for (int off = 128; off > 0; off >>= 1) {
        if (threadIdx.x < off) s[threadIdx.x] += s[threadIdx.x + off];
        __syncthreads();
    }
    if (threadIdx.x == 0) g_bsum[blockIdx.x] = s[0];
}

__global__ void scan_top_kernel() {
    __shared__ int s[256];
    int t = threadIdx.x;
    int v = (t < SCAN_BLKS) ? g_bsum[t] : 0;
    s[t] = v;
    __syncthreads();
    #pragma unroll
    for (int off = 1; off < 256; off <<= 1) {
        int u = (t >= off) ? s[t - off] : 0;
        __syncthreads();
        s[t] += u;
        __syncthreads();
    }
    if (t < SCAN_BLKS) g_boff[t] = s[t] - v;   // exclusive
}

__global__ void scan_final_kernel() {
    __shared__ int s[256];
    int t = threadIdx.x;
    int i = blockIdx.x * 256 + t;
    int v = g_deg[i];
    s[t] = v;
    __syncthreads();
    #pragma unroll
    for (int off = 1; off < 256; off <<= 1) {
        int u = (t >= off) ? s[t - off] : 0;
        __syncthreads();
        s[t] += u;
        __syncthreads();
    }
    int excl = s[t] - v + g_boff[blockIdx.x];
    if (i < NN) {
        g_rowptr[i] = excl;
        g_wpos[i]   = excl;
    }
    if (blockIdx.x == SCAN_BLKS - 1 && t == 255)
        g_rowptr[NN] = EE;
}

__global__ void csr_scatter_kernel(const int* __restrict__ src, const int* __restrict__ dst) {
    int e = blockIdx.x * blockDim.x + threadIdx.x;
    if (e >= EE) return;
    int pos = atomicAdd(&g_wpos[dst[e]], 1);
    g_srcs[pos] = src[e];
}

// ---------------- weight prep: both layers, concat + bf16 round ----------------
__global__ void prep_w_kernel(const float* __restrict__ Wq, const float* __restrict__ Wk,
                              const float* __restrict__ Wv, const float* __restrict__ Ws,
                              const float* __restrict__ bq, const float* __restrict__ bk,
                              const float* __restrict__ bv, const float* __restrict__ bs)
{
    int l = blockIdx.y;
    int i = blockIdx.x * 256 + threadIdx.x;
    if (i < DD * NCAT) {
        int k = i >> 9, nc = i & (NCAT - 1);
        int o = nc >> 7, n = nc & 127;
        const float* W = (o == 0) ? Wq : (o == 1) ? Wk : (o == 2) ? Wv : Ws;
        g_whb[l * DD * NCAT + i] = __float2bfloat16(W[l * DD * CC + k * CC + n]);
    }
    if (i < NCAT) {
        int o = i >> 7, n = i & 127;
        const float* B = (o == 0) ? bq : (o == 1) ? bk : (o == 2) ? bv : bs;
        g_bcat[l * NCAT + i] = B[l * CC + n];
    }
}

// ---------------- wmma bf16 GEMM: Y[:, o*128:+128] = X @ W + b ----------------
// 8 warps (4x2), warp tile 32x64, m16n16k16 bf16, fp32 accumulate.
// smem: sA bf16[128][40] | sB bf16[32][136] | sBias f32[16][132]; epilogue stage
// f32[128][68] reuses sbuf. Total 34816 B.
#define SAB_ELEMS (128 * 40)           // bf16
#define SBB_ELEMS (32 * 136)           // bf16
#define SBIAS_OFF ((SAB_ELEMS + SBB_ELEMS) / 2)   // float offset = 4736

__global__ __launch_bounds__(256, 2) void gemm_wmma_kernel(
    const float* __restrict__ X,   // null => g_h0 (post-relu, padded)
    int layer)
{
    __shared__ __align__(16) float sbuf[8704];   // 34816 B
    __nv_bfloat16* sA = reinterpret_cast<__nv_bfloat16*>(sbuf);
    __nv_bfloat16* sB = reinterpret_cast<__nv_bfloat16*>(sbuf) + SAB_ELEMS;
    float* sBias = sbuf + SBIAS_OFF;

    const int tid = threadIdx.x;
    const int w   = tid >> 5;
    const int wr  = w >> 1;          // 0..3 : rows wr*32..+32
    const int wc  = w & 1;           // 0..1 : cols wc*64..+64
    const int o   = blockIdx.y;
    const int row0 = blockIdx.x * 128;
    const bool guard = (X != nullptr);   // layer-0 input x has exactly NN rows
    const float* Xp = guard ? X : g_h0;
    const __nv_bfloat16* Wlb = g_whb + (size_t)layer * DD * NCAT;

    for (int i = tid; i < 16 * 128; i += 256) {
        int r = i >> 7, c = i & 127;
        sBias[r * 132 + c] = g_bcat[layer * NCAT + o * 128 + c];
    }
    __syncthreads();

    wmma::fragment<wmma::accumulator, 16, 16, 16, float> acc[2][4];
    #pragma unroll
    for (int i = 0; i < 2; i++)
        #pragma unroll
        for (int j = 0; j < 4; j++)
            wmma::load_matrix_sync(acc[i][j], &sBias[wc * 64 + j * 16], 132, wmma::mem_row_major);

    for (int k0 = 0; k0 < DD; k0 += 32) {
        __syncthreads();
        // A chunk: rows 0..127, cols k0..k0+31, fp32 -> bf16 on store
        #pragma unroll
        for (int i = tid; i < 1024; i += 256) {
            int r = i >> 3, c4 = i & 7;
            float4 v = make_float4(0.f, 0.f, 0.f, 0.f);
            if (!guard || row0 + r < NN)
                v = reinterpret_cast<const float4*>(Xp)[(size_t)(row0 + r) * 32 + (k0 >> 2) + c4];
            __nv_bfloat162 b0 = __floats2bfloat162_rn(v.x, v.y);
            __nv_bfloat162 b1 = __floats2bfloat162_rn(v.z, v.w);
            *reinterpret_cast<__nv_bfloat162*>(&sA[r * 40 + c4 * 4])     = b0;
            *reinterpret_cast<__nv_bfloat162*>(&sA[r * 40 + c4 * 4 + 2]) = b1;
        }
        // B chunk: rows k0..k0+31, cols o*128..+128 (already bf16), 16B copies
        #pragma unroll
        for (int i = tid; i < 512; i += 256) {
            int r = i >> 4, c8 = i & 15;
            *reinterpret_cast<uint4*>(&sB[r * 136 + c8 * 8]) =
                *reinterpret_cast<const uint4*>(&Wlb[(size_t)(k0 + r) * NCAT + o * 128 + c8 * 8]);
        }
        __syncthreads();

        #pragma unroll
        for (int kk = 0; kk < 32; kk += 16) {
            wmma::fragment<wmma::matrix_b, 16, 16, 16, __nv_bfloat16, wmma::row_major> bf[4];
            #pragma unroll
            for (int j = 0; j < 4; j++)
                wmma::load_matrix_sync(bf[j], &sB[kk * 136 + wc * 64 + j * 16], 136);
            #pragma unroll
            for (int i = 0; i < 2; i++) {
                wmma::fragment<wmma::matrix_a, 16, 16, 16, __nv_bfloat16, wmma::row_major> af;
                wmma::load_matrix_sync(af, &sA[(wr * 32 + i * 16) * 40 + kk], 40);
                #pragma unroll
                for (int j = 0; j < 4; j++)
                    wmma::mma_sync(acc[i][j], af, bf[j], acc[i][j]);
            }
        }
    }

    if (o == 3) {
        float* O = (layer == 0) ? g_h0 : g_h1;
        #pragma unroll
        for (int i = 0; i < 2; i++)
            #pragma unroll
            for (int j = 0; j < 4; j++)
                wmma::store_matrix_sync(
                    O + (size_t)(row0 + wr * 32 + i * 16) * CC + wc * 64 + j * 16,
                    acc[i][j], CC, wmma::mem_row_major);
    } else {
        // q (o==0) / k (o==1) / v (o==2): stage half-tile in smem, convert to bf16
        __nv_bfloat162* dstb = (o == 0)
            ? reinterpret_cast<__nv_bfloat162*>(g_qb)
            : reinterpret_cast<__nv_bfloat162*>(g_kv);
        const int rstride2  = (o == 0) ? 64 : 128;
        const int colbase2  = (o == 2) ? 64 : 0;
        float* stage = sbuf;                      // 128 x 68 floats = 34816 B (full sbuf)
        #pragma unroll
        for (int p = 0; p < 2; p++) {
            __syncthreads();
            if (wc == p) {
                #pragma unroll
                for (int i = 0; i < 2; i++)
                    #pragma unroll
                    for (int j = 0; j < 4; j++)
                        wmma::store_matrix_sync(
                            &stage[(size_t)(wr * 32 + i * 16) * 68 + j * 16],
                            acc[i][j], 68, wmma::mem_row_major);
            }
            __syncthreads();
            #pragma unroll
            for (int i = tid; i < 4096; i += 256) {
                int r = i >> 5, c2 = i & 31;      // 32 bf16x2 per 64-col half
                float lo = stage[r * 68 + c2 * 2];
                float hi = stage[r * 68 + c2 * 2 + 1];
                __nv_bfloat162 h2 = __floats2bfloat162_rn(lo, hi);
                dstb[(size_t)(row0 + r) * rstride2 + colbase2 + p * 32 + c2] = h2;
            }
        }
    }
}

// ---------------- fused attention: warp per dst node, online softmax, unroll 4 ----
__device__ __forceinline__ void kv_unpack(uint2 u, float2& a, float2& b) {
    a = __bfloat1622float2(*reinterpret_cast<__nv_bfloat162*>(&u.x));
    b = __bfloat1622float2(*reinterpret_cast<__nv_bfloat162*>(&u.y));
}

__device__ __forceinline__ void online_update(
    float sc, float2 va, float2 vb, float& m, float& den, float4& acc)
{
    float mn = fmaxf(m, sc);
    float corr = __expf(m - mn);
    float wgt = __expf(sc - mn);
    den = den * corr + wgt;
    acc.x = acc.x * corr + wgt * va.x;
    acc.y = acc.y * corr + wgt * va.y;
    acc.z = acc.z * corr + wgt * vb.x;
    acc.w = acc.w * corr + wgt * vb.y;
    m = mn;
}

__global__ __launch_bounds__(256) void attn_kernel(int layer, const int* __restrict__ batch)
{
    int t = blockIdx.x * 256 + threadIdx.x;
    int d = t >> 5;
    int lane = t & 31;
    if (d >= NN) return;
    int beg = g_rowptr[d];
    int end = g_rowptr[d + 1];

    uint2 uq = reinterpret_cast<const uint2*>(g_qb)[(size_t)d * 32 + lane];
    float2 qa_, qb_;
    kv_unpack(uq, qa_, qb_);
    float4 qa = make_float4(qa_.x, qa_.y, qb_.x, qb_.y);

    float m = -INFINITY;
    float den = 0.0f;
    float4 acc = make_float4(0.f, 0.f, 0.f, 0.f);

    const uint2* kvb = reinterpret_cast<const uint2*>(g_kv);  // node row = 64 uint2

    int e = beg;
    for (; e + 4 <= end; e += 4) {
        int s0 = g_srcs[e],     s1 = g_srcs[e + 1];
        int s2 = g_srcs[e + 2], s3 = g_srcs[e + 3];
        uint2 uk0 = kvb[(size_t)s0 * 64 + lane];
        uint2 uk1 = kvb[(size_t)s1 * 64 + lane];
        uint2 uk2 = kvb[(size_t)s2 * 64 + lane];
        uint2 uk3 = kvb[(size_t)s3 * 64 + lane];
        uint2 uv0 = kvb[(size_t)s0 * 64 + 32 + lane];
        uint2 uv1 = kvb[(size_t)s1 * 64 + 32 + lane];
        uint2 uv2 = kvb[(size_t)s2 * 64 + 32 + lane];
        uint2 uv3 = kvb[(size_t)s3 * 64 + 32 + lane];
        float2 ka0, kb0, ka1, kb1, ka2, kb2, ka3, kb3;
        kv_unpack(uk0, ka0, kb0); kv_unpack(uk1, ka1, kb1);
        kv_unpack(uk2, ka2, kb2); kv_unpack(uk3, ka3, kb3);
        float d0 = qa.x * ka0.x + qa.y * ka0.y + qa.z * kb0.x + qa.w * kb0.y;
        float d1 = qa.x * ka1.x + qa.y * ka1.y + qa.z * kb1.x + qa.w * kb1.y;
        float d2 = qa.x * ka2.x + qa.y * ka2.y + qa.z * kb2.x + qa.w * kb2.y;
        float d3 = qa.x * ka3.x + qa.y * ka3.y + qa.z * kb3.x + qa.w * kb3.y;
        #pragma unroll
        for (int o = 16; o > 0; o >>= 1) {
            d0 += __shfl_xor_sync(0xffffffffu, d0, o);
            d1 += __shfl_xor_sync(0xffffffffu, d1, o);
            d2 += __shfl_xor_sync(0xffffffffu, d2, o);
            d3 += __shfl_xor_sync(0xffffffffu, d3, o);
        }
        float2 va, vb;
        kv_unpack(uv0, va, vb);
        online_update(d0 * 0.08838834764831843f, va, vb, m, den, acc);
        kv_unpack(uv1, va, vb);
        online_update(d1 * 0.08838834764831843f, va, vb, m, den, acc);
        kv_unpack(uv2, va, vb);
        online_update(d2 * 0.08838834764831843f, va, vb, m, den, acc);
        kv_unpack(uv3, va, vb);
        online_update(d3 * 0.08838834764831843f, va, vb, m, den, acc);
    }
    for (; e < end; e++) {
        int s = g_srcs[e];
        uint2 uk = kvb[(size_t)s * 64 + lane];
        uint2 uv = kvb[(size_t)s * 64 + 32 + lane];
        float2 ka, kb;
        kv_unpack(uk, ka, kb);
        float dot = qa.x * ka.x + qa.y * ka.y + qa.z * kb.x + qa.w * kb.y;
        #pragma unroll
        for (int o = 16; o > 0; o >>= 1) dot += __shfl_xor_sync(0xffffffffu, dot, o);
        float2 va, vb;
        kv_unpack(uv, va, vb);
        online_update(dot * 0.08838834764831843f, va, vb, m, den, acc);
    }

    float* O = (layer == 0) ? g_h0 : g_h1;
    float4 o = reinterpret_cast<const float4*>(O)[(size_t)d * 32 + lane];
    if (beg < end) {
        float inv = 1.0f / den;
        o.x += acc.x * inv;
        o.y += acc.y * inv;
        o.z += acc.z * inv;
        o.w += acc.w * inv;
    }
    o.x = fmaxf(o.x, 0.f); o.y = fmaxf(o.y, 0.f);
    o.z = fmaxf(o.z, 0.f); o.w = fmaxf(o.w, 0.f);

    if (batch == nullptr) {
        reinterpret_cast<float4*>(O)[(size_t)d * 32 + lane] = o;
    } else {
        int g = batch[d];
        red_add_v4(&g_sums[g * CC + lane * 4], o.x, o.y, o.z, o.w);
        if (lane == 0) atomicAdd(&g_cnt[g], 1.0f);
    }
}

// ---------------- classifier + log_softmax ----------------
__global__ void final_kernel(const float* __restrict__ W_fc,
                             const float* __restrict__ b_fc,
                             float* __restrict__ out)
{
    int g = blockIdx.x;
    int j = threadIdx.x;
    __shared__ float sl[12];
    float inv = 1.0f / fmaxf(g_cnt[g], 1.0f);
    if (j < NCLS) {
        float acc = b_fc[j];
        for (int c = 0; c < CC; c++)
            acc += g_sums[g * CC + c] * inv * W_fc[c * NCLS + j];
        sl[j] = acc;
    }
    __syncwarp();
    if (j == 0) {
        float mx = sl[0];
        for (int i = 1; i < NCLS; i++) mx = fmaxf(mx, sl[i]);
        float ssum = 0.f;
        for (int i = 0; i < NCLS; i++) ssum += expf(sl[i] - mx);
        sl[10] = mx + logf(ssum);
    }
    __syncwarp();
    if (j < NCLS) out[g * NCLS + j] = sl[j] - sl[10];
}

// ---------------- launch ----------------
extern "C" void kernel_launch(void* const* d_in, const int* in_sizes, int n_in,
                              void* d_out, int out_size)
{
    const float* x    = (const float*)d_in[0];
    const int*   ei   = (const int*)d_in[1];
    const int*   batch= (const int*)d_in[2];
    const float* Wq   = (const float*)d_in[3];
    const float* bq   = (const float*)d_in[4];
    const float* Wk   = (const float*)d_in[5];
    const float* bk   = (const float*)d_in[6];
    const float* Wv   = (const float*)d_in[7];
    const float* bv   = (const float*)d_in[8];
    const float* Ws   = (const float*)d_in[9];
    const float* bs   = (const float*)d_in[10];
    const float* W_fc = (const float*)d_in[11];
    const float* b_fc = (const float*)d_in[12];
    float* out = (float*)d_out;

    const int* src = ei;
    const int* dst = ei + EE;

    // side stream + events for the CSR-build fork (created once; no device memory)
    static cudaStream_t s2 = nullptr;
    static cudaEvent_t evFork = nullptr, evJoin = nullptr;
    if (s2 == nullptr) {
        cudaStreamCreateWithFlags(&s2, cudaStreamNonBlocking);
        cudaEventCreateWithFlags(&evFork, cudaEventDisableTiming);
        cudaEventCreateWithFlags(&evJoin, cudaEventDisableTiming);
    }

    const int gemm_gx  = (NN + 127) / 128;          // 391
    const int edge_gx  = (EE + 255) / 256;          // 2344
    const int warp_gx  = (NN * 32 + 255) / 256;     // 6250
    const int prep_gx  = (DD * NCAT + 255) / 256;   // 256

    // fork for the CSR build; gemm0 kept at launch #4 so ncu profiles it.
    cudaEventRecord(evFork, 0);
    cudaStreamWaitEvent(s2, evFork, 0);

    prep_w_kernel<<<dim3(prep_gx, 2), 256>>>(Wq, Wk, Wv, Ws, bq, bk, bv, bs);   // #1
    init_pool_kernel<<<SCAN_BLKS, 256, 0, s2>>>();                              // #2
    csr_hist_kernel<<<edge_gx, 256, 0, s2>>>(dst);                              // #3
    gemm_wmma_kernel<<<dim3(gemm_gx, 4), 256>>>(x, 0);                          // #4 (profiled)
    scan_partial_kernel<<<SCAN_BLKS, 256, 0, s2>>>();
    scan_top_kernel<<<1, 256, 0, s2>>>();
    scan_final_kernel<<<SCAN_BLKS, 256, 0, s2>>>();
    csr_scatter_kernel<<<edge_gx, 256, 0, s2>>>(src, dst);
    cudaEventRecord(evJoin, s2);

    // join before attention consumes rowptr/srcs
    cudaStreamWaitEvent(0, evJoin, 0);
    attn_kernel<<<warp_gx, 256>>>(0, nullptr);
    gemm_wmma_kernel<<<dim3(gemm_gx, 4), 256>>>(nullptr, 1);
    attn_kernel<<<warp_gx, 256>>>(1, batch);     // fused mean-pool

    final_kernel<<<GG, 32>>>(W_fc, b_fc, out);
}